// round 7
// baseline (speedup 1.0000x reference)
#include <cuda_runtime.h>

// STRNNCell: out[b,h] = sigmoid( sum_c mask[b,c] * (x[b,c] @ tw[time[b,c]]) @ dw[dist[b,c]]
//                               + (h[b] @ hidden_weights) )
// B=256, C=50, INPUT=128, INTER=64, HIDDEN=128, slots=11.

namespace {
constexpr int Bv   = 256;
constexpr int Cv   = 50;
constexpr int INv  = 128;
constexpr int ITv  = 64;
constexpr int HIDv = 128;
constexpr int NSv  = 11;
constexpr int GSZ  = 4;    // contexts per time-slot group (shared tw load)
}

__global__ __launch_bounds__(256, 2)
void strnn_kernel(const float* __restrict__ x,          // (B,C,IN)
                  const int*   __restrict__ tctx,       // (B,C)
                  const int*   __restrict__ dctx,       // (B,C)
                  const unsigned char* __restrict__ mraw, // (B,C) bool OR int32
                  const float* __restrict__ hin,        // (B,HID)
                  const float* __restrict__ tw,         // (NS,IN,IT)
                  const float* __restrict__ dw,         // (NS,IT,HID)
                  const float* __restrict__ hw,         // (HID,HID)
                  float* __restrict__ out)              // (B,HID)
{
    __shared__ __align__(16) float xs[Cv * INv];      // 25.6 KB
    __shared__ __align__(16) float ts[Cv * ITv];      // 12.8 KB
    __shared__ __align__(16) float U [NSv * ITv];     // 2.8 KB
    __shared__ __align__(16) float hs[HIDv];
    __shared__ __align__(16) float2 red2[4 * 64];     // partials (4 squads x 128 floats)
    __shared__ int tlist[NSv][Cv];
    __shared__ int tcnt[NSv];
    __shared__ int dcs[Cv];
    __shared__ int mk[Cv];
    __shared__ int gslot[24], gbase[24], gn[24];
    __shared__ int ngroups;
    __shared__ unsigned char dused[NSv];

    const int tid = threadIdx.x;
    const int b   = blockIdx.x;

    // ---- mask dtype detection (bool bytes vs int32) ----
    // If stored as int32, every word of the buffer is 0 or 1.
    // If stored as packed bool bytes, words like 0x00000100 (>1) appear
    // with overwhelming probability in the first 128 entries.
    unsigned int wv = ((const unsigned int*)mraw)[tid & 31];
    const int mask_is_i32 = !__syncthreads_or((int)(wv > 1u));

    // ---- init + stage x, h ----
    if (tid < NSv) { tcnt[tid] = 0; dused[tid] = 0; }
    if (tid == 0) ngroups = 0;
    for (int i = tid; i < Cv * INv; i += 256) xs[i] = x[b * Cv * INv + i];
    if (tid < HIDv) hs[tid] = hin[b * HIDv + tid];
    __syncthreads();

    // ---- build per-time-slot lists of masked contexts ----
    if (tid < Cv) {
        const int c = tid;
        const int m = mask_is_i32 ? (((const int*)mraw)[b * Cv + c] != 0)
                                  : (mraw[b * Cv + c] != 0);
        mk[c] = m;
        const int d_ = dctx[b * Cv + c];
        dcs[c] = d_;
        if (m) {
            const int s = tctx[b * Cv + c];
            const int p = atomicAdd(&tcnt[s], 1);
            tlist[s][p] = c;
            dused[d_] = 1;
        }
    }
    __syncthreads();

    if (tid == 0) {
        int ng = 0;
        for (int s = 0; s < NSv; s++)
            for (int off = 0; off < tcnt[s]; off += GSZ) {
                gslot[ng] = s;
                gbase[ng] = off;
                gn[ng]    = min(GSZ, tcnt[s] - off);
                ng++;
            }
        ngroups = ng;   // <= ceil((50+3*11)/4) = 20
    }
    __syncthreads();

    // ---- phase 2: t[c] = x[b,c] @ tw[s], GSZ contexts share each weight load ----
    {
        const int warp = tid >> 5, lane = tid & 31;
        const int ng = ngroups;
        for (int g = warp; g < ng; g += 8) {
            const int s = gslot[g], base = gbase[g], n = gn[g];
            const float2* __restrict__ w2 = (const float2*)(tw + s * INv * ITv);
            int cc[GSZ];
            #pragma unroll
            for (int k = 0; k < GSZ; k++) cc[k] = tlist[s][base + (k < n ? k : 0)];
            float2 a[GSZ];
            #pragma unroll
            for (int k = 0; k < GSZ; k++) a[k] = make_float2(0.f, 0.f);
            #pragma unroll 4
            for (int i = 0; i < INv; i++) {
                const float2 w = w2[i * 32 + lane];   // coalesced: lane-consecutive
                #pragma unroll
                for (int k = 0; k < GSZ; k++) {
                    const float xv = xs[cc[k] * INv + i];  // smem broadcast
                    a[k].x = fmaf(xv, w.x, a[k].x);
                    a[k].y = fmaf(xv, w.y, a[k].y);
                }
            }
            #pragma unroll
            for (int k = 0; k < GSZ; k++)
                if (k < n) ((float2*)ts)[cc[k] * (ITv / 2) + lane] = a[k];
        }
    }
    __syncthreads();

    // ---- phase 3: U[s] = sum over masked c with dist==s of t[c]  (deterministic order) ----
    {
        const int j = tid & 63, sq = tid >> 6;
        for (int s = sq; s < NSv; s += 4) {
            float u = 0.f;
            for (int c = 0; c < Cv; c++)
                if (mk[c] && dcs[c] == s) u += ts[c * ITv + j];
            U[s * ITv + j] = u;
        }
    }
    __syncthreads();

    // ---- phase 4: xc = sum_s U[s] @ dw[s]   (+ phase 5: h @ hw) ----
    {
        const int h2 = tid & 63, sq = tid >> 6;
        float2 acc = make_float2(0.f, 0.f);
        const float2* __restrict__ dw2 = (const float2*)dw;
        for (int s = sq; s < NSv; s += 4) {
            if (!dused[s]) continue;
            const float2* __restrict__ wrow = dw2 + s * ITv * (HIDv / 2);
            #pragma unroll 4
            for (int j = 0; j < ITv; j++) {
                const float uj = U[s * ITv + j];
                const float2 w = wrow[j * (HIDv / 2) + h2];  // coalesced
                acc.x = fmaf(uj, w.x, acc.x);
                acc.y = fmaf(uj, w.y, acc.y);
            }
        }
        const float2* __restrict__ hw2 = (const float2*)hw;
        #pragma unroll 4
        for (int k = sq * 32; k < sq * 32 + 32; k++) {
            const float hv = hs[k];
            const float2 w = hw2[k * (HIDv / 2) + h2];
            acc.x = fmaf(hv, w.x, acc.x);
            acc.y = fmaf(hv, w.y, acc.y);
        }
        red2[sq * 64 + h2] = acc;
    }
    __syncthreads();

    // ---- final reduce + sigmoid ----
    if (tid < HIDv) {
        const float* rf = (const float*)red2;
        const float z = rf[tid] + rf[128 + tid] + rf[256 + tid] + rf[384 + tid];
        out[b * HIDv + tid] = 1.f / (1.f + expf(-z));
    }
}

extern "C" void kernel_launch(void* const* d_in, const int* in_sizes, int n_in,
                              void* d_out, int out_size) {
    (void)in_sizes; (void)n_in; (void)out_size;
    strnn_kernel<<<Bv, 256>>>(
        (const float*)d_in[0],
        (const int*)d_in[1],
        (const int*)d_in[2],
        (const unsigned char*)d_in[3],
        (const float*)d_in[4],
        (const float*)d_in[5],
        (const float*)d_in[6],
        (const float*)d_in[7],
        (float*)d_out);
}